// round 4
// baseline (speedup 1.0000x reference)
#include <cuda_runtime.h>
#include <cstdint>

// z_e: [32, 64, 64, 64] fp32  -> N = 131072 rows (b,h,w), D = 64 channels
// codebook: [512, 64] fp32
// out: z_q (N*D fp32) then indices (N, as fp32 values)
#define NROWS   131072
#define DDIM    64
#define KCB     512
#define TPB     512
#define NCTAS   (NROWS / TPB)   // 256 CTAs, 1 row per thread

// Replicate XLA-GPU row-reduction tree for a 64-elem f32 row of squares:
//   vector_size=2: t[l] = fl(x[2l]*x[2l] + x[2l+1]*x[2l+1]),  l = 0..31
//   then shfl_down offsets 16,8,4,2,1:  s_l += s_{l+off}
// All adds/muls separately rounded (no FMA contraction).
__device__ __forceinline__ float xla_row_sumsq(const float* __restrict__ x)
{
    float t[32];
    #pragma unroll
    for (int l = 0; l < 32; ++l)
        t[l] = __fadd_rn(__fmul_rn(x[2 * l], x[2 * l]),
                         __fmul_rn(x[2 * l + 1], x[2 * l + 1]));
    #pragma unroll
    for (int off = 16; off >= 1; off >>= 1)
        #pragma unroll
        for (int l = 0; l < off; ++l)
            t[l] = __fadd_rn(t[l], t[l + off]);
    return t[0];
}

__global__ __launch_bounds__(TPB, 1)
void vq_kernel(const float* __restrict__ z_e,
               const float* __restrict__ cb,
               float* __restrict__ out,
               int write_idx)
{
    extern __shared__ float smem[];
    float* s_cb  = smem;               // [K*D] = 128 KB
    float* s_nrm = smem + KCB * DDIM;  // [K]

    // Stage codebook into SMEM
    for (int i = threadIdx.x; i < (KCB * DDIM) / 4; i += TPB)
        ((float4*)s_cb)[i] = ((const float4*)cb)[i];
    __syncthreads();

    // ||e_k||^2 with the same XLA reduction tree
    for (int k = threadIdx.x; k < KCB; k += TPB)
        s_nrm[k] = xla_row_sumsq(s_cb + k * DDIM);
    __syncthreads();

    const int row = blockIdx.x * TPB + threadIdx.x;

    // Gather this row from NCHW layout: addr(n,c) = (n>>12)*262144 + c*4096 + (n&4095)
    float x[DDIM];
    {
        const long long base = (long long)(row >> 12) * 262144 + (row & 4095);
        #pragma unroll
        for (int c = 0; c < DDIM; ++c)
            x[c] = z_e[base + (long long)c * 4096];
    }

    // ||x||^2 with the XLA reduction tree (the grid-critical term)
    const float xn = xla_row_sumsq(x);

    float best = 3.402823466e38f;
    int   bi   = 0;

    for (int k = 0; k < KCB; ++k) {
        const float4* cr = (const float4*)(s_cb + k * DDIM);
        // dot(x, e_k): fp32 FMA chain (sub-grid accurate vs cublas; order-insensitive
        // at the dist quantization granularity)
        float dot = 0.f;
        #pragma unroll
        for (int j = 0; j < DDIM / 4; ++j) {
            float4 c4 = cr[j];                       // LDS.128 broadcast
            dot = fmaf(x[4 * j + 0], c4.x, dot);
            dot = fmaf(x[4 * j + 1], c4.y, dot);
            dot = fmaf(x[4 * j + 2], c4.z, dot);
            dot = fmaf(x[4 * j + 3], c4.w, dot);
        }
        // Reference rounding: dist = fl( fl(xn + en) - fl(2*dot) )
        const float dist = __fsub_rn(__fadd_rn(xn, s_nrm[k]), __fmul_rn(2.f, dot));
        if (dist < best) { best = dist; bi = k; }    // strict < == first-index ties
    }

    // z_q gather (raw reshape => identity layout)
    {
        const float4* r = (const float4*)(s_cb + bi * DDIM);
        float4* o = (float4*)(out + (size_t)row * DDIM);
        #pragma unroll
        for (int j = 0; j < DDIM / 4; ++j) o[j] = r[j];
    }
    if (write_idx)
        out[(size_t)NROWS * DDIM + row] = (float)bi;
}

extern "C" void kernel_launch(void* const* d_in, const int* in_sizes, int n_in,
                              void* d_out, int out_size)
{
    const float* z_e = (const float*)d_in[0];
    const float* cb  = (const float*)d_in[1];
    if (n_in >= 2 && in_sizes[0] == KCB * DDIM && in_sizes[1] == NROWS * DDIM) {
        const float* t = z_e; z_e = cb; cb = t;   // defensive input-order swap
    }
    const int write_idx = (out_size >= NROWS * DDIM + NROWS) ? 1 : 0;

    const int smem_bytes = (KCB * DDIM + KCB) * (int)sizeof(float);  // 132 KB
    cudaFuncSetAttribute(vq_kernel, cudaFuncAttributeMaxDynamicSharedMemorySize,
                         smem_bytes);
    vq_kernel<<<NCTAS, TPB, smem_bytes>>>(z_e, cb, (float*)d_out, write_idx);
}

// round 6
// speedup vs baseline: 1.2907x; 1.2907x over previous
#include <cuda_runtime.h>
#include <cstdint>

// z_e: [32, 64, 64, 64] fp32  -> N = 131072 rows (b,h,w), D = 64 channels
// codebook: [512, 64] fp32
// out: z_q (N*D fp32) then indices (N, as fp32 values)
#define NROWS   131072
#define DDIM    64
#define KCB     512
#define TPB     256
#define NCTAS   148
#define RPC     ((NROWS + NCTAS - 1) / NCTAS)   // 886 rows per CTA
#define CHUNK   (TPB * 2)                        // 512 rows per pass (2 rows/thread)

// SACRED: XLA-GPU row-reduction tree for sum of squares over 64 f32 values.
//   t[l] = fl(x[2l]^2 + x[2l+1]^2), l=0..31; then pairwise tree offs 16,8,4,2,1.
// No FMA contraction anywhere. Matches reference bitwise (proven R4, rel_err==0).
__device__ __forceinline__ float xla_row_sumsq(const float* __restrict__ x)
{
    float t[32];
    #pragma unroll
    for (int l = 0; l < 32; ++l)
        t[l] = __fadd_rn(__fmul_rn(x[2 * l], x[2 * l]),
                         __fmul_rn(x[2 * l + 1], x[2 * l + 1]));
    #pragma unroll
    for (int off = 16; off >= 1; off >>= 1)
        #pragma unroll
        for (int l = 0; l < off; ++l)
            t[l] = __fadd_rn(t[l], t[l + off]);
    return t[0];
}

__global__ __launch_bounds__(TPB, 1)
void vq_kernel(const float* __restrict__ z_e,
               const float* __restrict__ cb,
               float* __restrict__ out,
               int write_idx)
{
    extern __shared__ float smem[];
    float* s_cb  = smem;               // [K*D] = 128 KB
    float* s_nrm = smem + KCB * DDIM;  // [K]

    // Stage codebook into SMEM
    for (int i = threadIdx.x; i < (KCB * DDIM) / 4; i += TPB)
        ((float4*)s_cb)[i] = ((const float4*)cb)[i];
    __syncthreads();

    // ||e_k||^2 with the same XLA reduction tree (SACRED rounding)
    for (int k = threadIdx.x; k < KCB; k += TPB)
        s_nrm[k] = xla_row_sumsq(s_cb + k * DDIM);
    __syncthreads();

    const int row_begin = blockIdx.x * RPC;
    const int row_end   = min(row_begin + RPC, NROWS);

    for (int base = row_begin; base < row_end; base += CHUNK) {
        const int r0 = base + threadIdx.x;
        const int r1 = r0 + TPB;
        const bool act0 = (r0 < row_end);
        const bool act1 = (r1 < row_end);

        // Gather rows from NCHW: addr(n,c) = (n>>12)*262144 + c*4096 + (n&4095)
        float x0[DDIM], x1[DDIM];
        {
            const long long a0 = (long long)(r0 >> 12) * 262144 + (r0 & 4095);
            const long long a1 = (long long)(r1 >> 12) * 262144 + (r1 & 4095);
            #pragma unroll
            for (int c = 0; c < DDIM; ++c) {
                x0[c] = act0 ? z_e[a0 + (long long)c * 4096] : 0.f;
                x1[c] = act1 ? z_e[a1 + (long long)c * 4096] : 0.f;
            }
        }
        // SACRED: ||x||^2 via the XLA tree
        const float xn0 = xla_row_sumsq(x0);
        const float xn1 = xla_row_sumsq(x1);

        float best0 = 3.402823466e38f, best1 = 3.402823466e38f;
        int   bi0 = 0, bi1 = 0;

        for (int k = 0; k < KCB; ++k) {
            const float4* cr = (const float4*)(s_cb + k * DDIM);
            // 4 independent FMA chains per row; one LDS.128 feeds 8 FMAs.
            float p00 = 0.f, p01 = 0.f, p02 = 0.f, p03 = 0.f;
            float p10 = 0.f, p11 = 0.f, p12 = 0.f, p13 = 0.f;
            #pragma unroll
            for (int j = 0; j < DDIM / 4; ++j) {
                const float4 c4 = cr[j];            // LDS.128 broadcast
                p00 = fmaf(x0[4 * j + 0], c4.x, p00);
                p01 = fmaf(x0[4 * j + 1], c4.y, p01);
                p02 = fmaf(x0[4 * j + 2], c4.z, p02);
                p03 = fmaf(x0[4 * j + 3], c4.w, p03);
                p10 = fmaf(x1[4 * j + 0], c4.x, p10);
                p11 = fmaf(x1[4 * j + 1], c4.y, p11);
                p12 = fmaf(x1[4 * j + 2], c4.z, p12);
                p13 = fmaf(x1[4 * j + 3], c4.w, p13);
            }
            // dot order is free (sub-grid accurate; proven R4)
            const float dot0 = (p00 + p01) + (p02 + p03);
            const float dot1 = (p10 + p11) + (p12 + p13);
            const float en = s_nrm[k];
            // SACRED final rounding: dist = fl( fl(xn + en) - fl(2*dot) )
            const float d0 = __fsub_rn(__fadd_rn(xn0, en), __fmul_rn(2.f, dot0));
            const float d1 = __fsub_rn(__fadd_rn(xn1, en), __fmul_rn(2.f, dot1));
            if (d0 < best0) { best0 = d0; bi0 = k; }   // strict < == first-index ties
            if (d1 < best1) { best1 = d1; bi1 = k; }
        }

        // z_q gather (raw reshape => identity layout)
        if (act0) {
            const float4* r = (const float4*)(s_cb + bi0 * DDIM);
            float4* o = (float4*)(out + (size_t)r0 * DDIM);
            #pragma unroll
            for (int j = 0; j < DDIM / 4; ++j) o[j] = r[j];
        }
        if (act1) {
            const float4* r = (const float4*)(s_cb + bi1 * DDIM);
            float4* o = (float4*)(out + (size_t)r1 * DDIM);
            #pragma unroll
            for (int j = 0; j < DDIM / 4; ++j) o[j] = r[j];
        }
        if (write_idx) {
            if (act0) out[(size_t)NROWS * DDIM + r0] = (float)bi0;
            if (act1) out[(size_t)NROWS * DDIM + r1] = (float)bi1;
        }
    }
}

extern "C" void kernel_launch(void* const* d_in, const int* in_sizes, int n_in,
                              void* d_out, int out_size)
{
    const float* z_e = (const float*)d_in[0];
    const float* cb  = (const float*)d_in[1];
    if (n_in >= 2 && in_sizes[0] == KCB * DDIM && in_sizes[1] == NROWS * DDIM) {
        const float* t = z_e; z_e = cb; cb = t;   // defensive input-order swap
    }
    const int write_idx = (out_size >= NROWS * DDIM + NROWS) ? 1 : 0;

    const int smem_bytes = (KCB * DDIM + KCB) * (int)sizeof(float);  // 132 KB
    cudaFuncSetAttribute(vq_kernel, cudaFuncAttributeMaxDynamicSharedMemorySize,
                         smem_bytes);
    vq_kernel<<<NCTAS, TPB, smem_bytes>>>(z_e, cb, (float*)d_out, write_idx);
}